// round 4
// baseline (speedup 1.0000x reference)
#include <cuda_runtime.h>
#include <cuda_bf16.h>
#include <cstdint>
#include <math.h>

#define NQ     65536
#define DIMIN  1024
#define DIMH   256
#define NCLUS  8
#define BM     128
#define BN     128
#define BK     64
#define NBLK   (NQ / BM)       // 512 row-blocks
#define NCTA   (NBLK * 2)      // 1024 CTAs (x2 N-halves)
#define NITER  (DIMIN / BK)    // 16

// smem layout (bytes)
#define LDA      144           // 64 bf16 (128B) + 16B pad per row
#define STAGE_A  (128 * LDA)   // 18432
#define STAGE_B  (128 * LDA)   // 18432
#define STAGE    (STAGE_A + STAGE_B)
#define OFF_A(s) ((unsigned)(s) * STAGE)
#define OFF_B(s) ((unsigned)(s) * STAGE + STAGE_A)
#define HLD      132
#define OFF_EXTRA 73728u       // end of 2 stages; hbuf (128*132*4=67584) unioned below
#define OFF_B1   OFF_EXTRA
#define OFF_CID  (OFF_B1 + 512u)
#define OFF_CNT  (OFF_CID + 512u)
#define SMEM_DYN (OFF_CNT + 32u)   // 74272 B -> 2 CTAs/SM

// ---- device scratch (no allocations allowed) ----
__device__ __nv_bfloat16 g_W1bf[DIMH * DIMIN];          // 512 KB
__device__ float g_scratch[1024 * NCLUS * DIMH];        // 8 MB [vb][cl][col]
__device__ int   g_scnt[NBLK * NCLUS];
__device__ float g_seg[NCLUS * DIMH];
__device__ int   g_cnt[NCLUS];
__device__ float g_hp[NCLUS * DIMH];
__device__ float g_part[NCLUS * 8];

// ---- helpers ----
__device__ __forceinline__ uint32_t smem_u32(const void* p) {
    uint32_t a;
    asm("{ .reg .u64 t; cvta.to.shared.u64 t, %1; cvt.u32.u64 %0, t; }" : "=r"(a) : "l"(p));
    return a;
}

__device__ __forceinline__ void ldm4(uint32_t* r, uint32_t addr) {
    asm volatile("ldmatrix.sync.aligned.m8n8.x4.shared.b16 {%0,%1,%2,%3}, [%4];"
                 : "=r"(r[0]), "=r"(r[1]), "=r"(r[2]), "=r"(r[3]) : "r"(addr));
}

__device__ __forceinline__ void mma_bf16(float* d, const uint32_t* a,
                                         uint32_t b0, uint32_t b1) {
    asm volatile("mma.sync.aligned.m16n8k16.row.col.f32.bf16.bf16.f32 "
                 "{%0,%1,%2,%3}, {%4,%5,%6,%7}, {%8,%9}, {%0,%1,%2,%3};"
                 : "+f"(d[0]), "+f"(d[1]), "+f"(d[2]), "+f"(d[3])
                 : "r"(a[0]), "r"(a[1]), "r"(a[2]), "r"(a[3]), "r"(b0), "r"(b1));
}

// B tile: 128 rows x 64 bf16 cols = 1024 x 16B chunks, 4 per thread
__device__ __forceinline__ void cp_B(uint32_t base, int s, int k0, int tid,
                                     const __nv_bfloat16* w1h) {
    uint32_t dst = base + OFF_B(s);
    const char* src = (const char*)w1h + (size_t)k0 * 2;
    #pragma unroll
    for (int i = 0; i < 4; i++) {
        int c  = tid + 256 * i;
        int n  = c >> 3, kc = c & 7;
        uint32_t d = dst + (unsigned)n * LDA + (unsigned)kc * 16;
        const void* g = src + (size_t)n * (DIMIN * 2) + kc * 16;
        asm volatile("cp.async.cg.shared.global [%0], [%1], 16;" :: "r"(d), "l"(g));
    }
}

// A half-tile (64 rows) load / store
__device__ __forceinline__ void ldgA(float4* areg, const float* x,
                                     int row0, int it, int tid, int h) {
    const int r0 = h * 64 + (tid >> 4), fc = tid & 15;
    const float* p = x + (size_t)(row0 + r0) * DIMIN + it * BK + fc * 4;
    #pragma unroll
    for (int i = 0; i < 4; i++)
        areg[i] = *(const float4*)(p + (size_t)(16 * i) * DIMIN);
}

__device__ __forceinline__ void stsA(uint32_t sA, const float4* areg, int tid, int h) {
    const int r0 = h * 64 + (tid >> 4), fc = tid & 15;
    #pragma unroll
    for (int i = 0; i < 4; i++) {
        __nv_bfloat162 lo = __floats2bfloat162_rn(areg[i].x, areg[i].y);
        __nv_bfloat162 hi = __floats2bfloat162_rn(areg[i].z, areg[i].w);
        uint32_t u0 = *(uint32_t*)&lo, u1 = *(uint32_t*)&hi;
        uint32_t d = sA + (unsigned)(r0 + 16 * i) * LDA + (unsigned)fc * 8;
        asm volatile("st.shared.v2.b32 [%0], {%1,%2};" :: "r"(d), "r"(u0), "r"(u1));
    }
}

// ---------------------------------------------------------------------------
// K0: W1 fp32 -> bf16
// ---------------------------------------------------------------------------
__global__ __launch_bounds__(256)
void k_w1cvt(const float* __restrict__ W1) {
    int i = (blockIdx.x * 256 + threadIdx.x) * 4;
    float4 v = *(const float4*)(W1 + i);
    __nv_bfloat162 lo = __floats2bfloat162_rn(v.x, v.y);
    __nv_bfloat162 hi = __floats2bfloat162_rn(v.z, v.w);
    uint2 u;
    u.x = *(uint32_t*)&lo;
    u.y = *(uint32_t*)&hi;
    *(uint2*)&g_W1bf[i] = u;
}

// ---------------------------------------------------------------------------
// K1: bf16 mma.sync GEMM (128x128 tile, 256 thr, 2 CTAs/SM) + cluster sums
//     blockIdx.x = rb*2 + nh
// ---------------------------------------------------------------------------
__global__ __launch_bounds__(256, 2)
void k_gemm_seg(const float* __restrict__ x, const int* __restrict__ cid,
                const float* __restrict__ b1)
{
    extern __shared__ char sm[];
    const uint32_t base = smem_u32(sm);
    float* b1s   = (float*)(sm + OFF_B1);
    int*   cid_s = (int*)  (sm + OFF_CID);
    int*   cnt_s = (int*)  (sm + OFF_CNT);

    const int tid  = threadIdx.x;
    const int lane = tid & 31, warp = tid >> 5;
    const int wn = warp & 3, wm = warp >> 2;       // 4 n-groups x 2 m-groups
    const int rb = blockIdx.x >> 1, nh = blockIdx.x & 1;
    const int row0 = rb * BM;
    const __nv_bfloat16* w1h = g_W1bf + (size_t)nh * BN * DIMIN;

    if (tid < 8)   cnt_s[tid] = 0;
    if (tid < 128) b1s[tid] = b1[nh * BN + tid];
    if (tid < 128) cid_s[tid] = cid[row0 + tid];

    float acc[4][4][4];
    #pragma unroll
    for (int mt = 0; mt < 4; mt++)
        #pragma unroll
        for (int nt = 0; nt < 4; nt++)
            #pragma unroll
            for (int q = 0; q < 4; q++) acc[mt][nt][q] = 0.0f;

    // prologue: stage 0
    float4 areg[4];
    cp_B(base, 0, 0, tid, w1h);
    asm volatile("cp.async.commit_group;" ::: "memory");
    ldgA(areg, x, row0, 0, tid, 0);
    stsA(base + OFF_A(0), areg, tid, 0);
    ldgA(areg, x, row0, 0, tid, 1);
    stsA(base + OFF_A(0), areg, tid, 1);
    asm volatile("cp.async.wait_group 0;" ::: "memory");
    __syncthreads();

    for (int it = 0; it < NITER; it++) {
        const int s = it & 1;
        const bool nxt = (it + 1 < NITER);
        if (nxt) {
            cp_B(base, s ^ 1, (it + 1) * BK, tid, w1h);
            asm volatile("cp.async.commit_group;" ::: "memory");
            ldgA(areg, x, row0, it + 1, tid, 0);
        }
        const uint32_t sA = base + OFF_A(s), sB = base + OFF_B(s);

        #pragma unroll
        for (int half = 0; half < 2; half++) {
            #pragma unroll
            for (int kq = 0; kq < 2; kq++) {
                const int ks = half * 2 + kq;
                uint32_t a[4][4];
                const uint32_t abase = sA + (unsigned)(wm * 64 + (lane & 15)) * LDA
                                     + (unsigned)ks * 32 + (unsigned)(lane >> 4) * 16;
                #pragma unroll
                for (int mt = 0; mt < 4; mt++)
                    ldm4(a[mt], abase + (unsigned)(mt * 16) * LDA);
                #pragma unroll
                for (int j = 0; j < 2; j++) {
                    uint32_t b[4];
                    ldm4(b, sB + (unsigned)(wn * 32 + j * 16 + (lane & 15)) * LDA
                              + (unsigned)ks * 32 + (unsigned)(lane >> 4) * 16);
                    #pragma unroll
                    for (int mt = 0; mt < 4; mt++) {
                        mma_bf16(acc[mt][2 * j],     a[mt], b[0], b[2]);
                        mma_bf16(acc[mt][2 * j + 1], a[mt], b[1], b[3]);
                    }
                }
            }
            if (nxt) {
                stsA(base + OFF_A(s ^ 1), areg, tid, half);
                if (half == 0) ldgA(areg, x, row0, it + 1, tid, 1);
                else asm volatile("cp.async.wait_group 0;" ::: "memory");
            }
        }
        __syncthreads();
    }

    // epilogue: accum -> smem hbuf (unioned with stage region)
    float* hbuf = (float*)sm;
    #pragma unroll
    for (int mt = 0; mt < 4; mt++)
        #pragma unroll
        for (int nt = 0; nt < 4; nt++) {
            int gm = wm * 64 + mt * 16 + (lane >> 2);
            int gn = wn * 32 + nt * 8 + 2 * (lane & 3);
            hbuf[gm * HLD + gn]           = acc[mt][nt][0];
            hbuf[gm * HLD + gn + 1]       = acc[mt][nt][1];
            hbuf[(gm + 8) * HLD + gn]     = acc[mt][nt][2];
            hbuf[(gm + 8) * HLD + gn + 1] = acc[mt][nt][3];
        }

    // per-CTA cluster counts (nh==0 half only, warps 0-3)
    if (nh == 0 && tid < 128) {
        int cidv = cid_s[tid];
        #pragma unroll
        for (int c = 0; c < 8; c++) {
            unsigned m = __ballot_sync(0xffffffffu, cidv == c);
            if (lane == c) atomicAdd(&cnt_s[c], __popc(m));
        }
    }
    __syncthreads();

    // bias + relu + cluster-masked column sums: thread = (col 0..127, rowhalf)
    const int ct = tid & 127, rh = tid >> 7;
    const float bt = b1s[ct];
    float sacc[NCLUS];
    #pragma unroll
    for (int c = 0; c < NCLUS; c++) sacc[c] = 0.0f;
    #pragma unroll 4
    for (int r = rh * 64; r < rh * 64 + 64; r++) {
        float v = fmaxf(hbuf[r * HLD + ct] + bt, 0.0f);
        int cd = cid_s[r];
        #pragma unroll
        for (int c = 0; c < NCLUS; c++) sacc[c] += (cd == c) ? v : 0.0f;
    }
    float* outp = g_scratch + ((size_t)(rb * 2 + rh)) * (NCLUS * DIMH) + nh * BN + ct;
    #pragma unroll
    for (int c = 0; c < NCLUS; c++) outp[c * DIMH] = sacc[c];
    if (nh == 0 && tid < 8) g_scnt[rb * 8 + tid] = cnt_s[tid];
}

// ---------------------------------------------------------------------------
// K2: reduce 1024 virtual-block partials -> g_seg ; counts -> g_cnt
// ---------------------------------------------------------------------------
__global__ __launch_bounds__(256)
void k_reduce()
{
    const int g0 = blockIdx.x * 32;
    const int jj = threadIdx.x & 31;
    const int bs = threadIdx.x >> 5;
    float s = 0.0f;
    #pragma unroll 4
    for (int b = bs; b < 1024; b += 8)
        s += g_scratch[(size_t)b * (NCLUS * DIMH) + g0 + jj];
    __shared__ float red[8][33];
    __shared__ int   credp[8][9];
    red[bs][jj] = s;
    if (blockIdx.x == 0 && threadIdx.x < 64) {
        int c = threadIdx.x & 7, sl = threadIdx.x >> 3, t = 0;
        for (int b = sl; b < NBLK; b += 8) t += g_scnt[b * 8 + c];
        credp[c][sl] = t;
    }
    __syncthreads();
    if (bs == 0) {
        float t = 0.0f;
        #pragma unroll
        for (int c = 0; c < 8; c++) t += red[c][jj];
        g_seg[g0 + jj] = t;
    }
    if (blockIdx.x == 0 && threadIdx.x < 8) {
        int T = 0;
        #pragma unroll
        for (int sl = 0; sl < 8; sl++) T += credp[threadIdx.x][sl];
        g_cnt[threadIdx.x] = T;
    }
}

// ---------------------------------------------------------------------------
// K3a: means + h_path = relu(hc @ Wf^T + bf)   grid 64 (8 clus x 8 row-groups)
// ---------------------------------------------------------------------------
__global__ __launch_bounds__(256)
void k_head1(const float* __restrict__ Wf, const float* __restrict__ bfv)
{
    const int c = blockIdx.x >> 3, og = blockIdx.x & 7, tid = threadIdx.x;
    __shared__ float hc_s[DIMH];
    float denom = fmaxf((float)g_cnt[c], 1.0f);
    hc_s[tid] = g_seg[c * DIMH + tid] * (1.0f / denom);
    __syncthreads();

    const int row = og * 32 + (tid >> 3);
    const int k0  = (tid & 7) * 32;
    const float4* w = (const float4*)(Wf + (size_t)row * DIMH + k0);
    float a = 0.0f;
    #pragma unroll
    for (int k = 0; k < 8; k++) {
        float4 wv = w[k];
        a += wv.x * hc_s[k0 + 4 * k]     + wv.y * hc_s[k0 + 4 * k + 1]
           + wv.z * hc_s[k0 + 4 * k + 2] + wv.w * hc_s[k0 + 4 * k + 3];
    }
    #pragma unroll
    for (int o = 4; o > 0; o >>= 1)
        a += __shfl_xor_sync(0xffffffffu, a, o);
    if ((tid & 7) == 0)
        g_hp[c * DIMH + row] = fmaxf(a + bfv[row], 0.0f);
}

// ---------------------------------------------------------------------------
// K3b: gated attention partial logits   grid 64 (8 clus x 8 row-groups)
// ---------------------------------------------------------------------------
__global__ __launch_bounds__(256)
void k_head2(const float* __restrict__ Wa, const float* __restrict__ ba,
             const float* __restrict__ Wb, const float* __restrict__ bb,
             const float* __restrict__ Wc)
{
    const int b = blockIdx.x, tid = threadIdx.x;
    const int c = b >> 3, rg = b & 7;
    __shared__ float hp_s[DIMH];
    hp_s[tid] = g_hp[c * DIMH + tid];
    __syncthreads();

    const int row = rg * 32 + (tid >> 3);
    const int k0  = (tid & 7) * 32;
    const float4* wa = (const float4*)(Wa + (size_t)row * DIMH + k0);
    const float4* wb = (const float4*)(Wb + (size_t)row * DIMH + k0);
    float aa = 0.0f, gg = 0.0f;
    #pragma unroll
    for (int k = 0; k < 8; k++) {
        float4 av = wa[k], bv = wb[k];
        float h0 = hp_s[k0 + 4 * k], h1 = hp_s[k0 + 4 * k + 1];
        float h2 = hp_s[k0 + 4 * k + 2], h3 = hp_s[k0 + 4 * k + 3];
        aa += av.x * h0 + av.y * h1 + av.z * h2 + av.w * h3;
        gg += bv.x * h0 + bv.y * h1 + bv.z * h2 + bv.w * h3;
    }
    #pragma unroll
    for (int o = 4; o > 0; o >>= 1) {
        aa += __shfl_xor_sync(0xffffffffu, aa, o);
        gg += __shfl_xor_sync(0xffffffffu, gg, o);
    }
    float val = 0.0f;
    if ((tid & 7) == 0) {
        aa += ba[row]; gg += bb[row];
        val = tanhf(aa) * (1.0f / (1.0f + expf(-gg))) * Wc[row];
    }
    val += __shfl_xor_sync(0xffffffffu, val, 8);
    val += __shfl_xor_sync(0xffffffffu, val, 16);
    __shared__ float wred[8];
    if ((tid & 31) == 0) wred[tid >> 5] = val;
    __syncthreads();
    if (tid == 0) {
        float t = 0.0f;
        #pragma unroll
        for (int w = 0; w < 8; w++) t += wred[w];
        g_part[c * 8 + rg] = t;
    }
}

// ---------------------------------------------------------------------------
// K3c: softmax over 8 logits + weighted sum -> out[256]
// ---------------------------------------------------------------------------
__global__ __launch_bounds__(256)
void k_final(const float* __restrict__ bc, float* __restrict__ out)
{
    const int tid = threadIdx.x;
    float l[NCLUS];
    #pragma unroll
    for (int c = 0; c < NCLUS; c++) {
        float t = bc[0];
        #pragma unroll
        for (int g = 0; g < 8; g++) t += g_part[c * 8 + g];
        l[c] = t;
    }
    float m = -1e30f;
    #pragma unroll
    for (int c = 0; c < NCLUS; c++) m = fmaxf(m, l[c]);
    float S = 0.0f;
    #pragma unroll
    for (int c = 0; c < NCLUS; c++) { l[c] = expf(l[c] - m); S += l[c]; }
    float o = 0.0f;
    #pragma unroll
    for (int c = 0; c < NCLUS; c++) o += l[c] * g_hp[c * DIMH + tid];
    out[tid] = o / S;
}

// ---------------------------------------------------------------------------
extern "C" void kernel_launch(void* const* d_in, const int* in_sizes, int n_in,
                              void* d_out, int out_size)
{
    const float* x   = (const float*)d_in[0];
    const int*   cid = (const int*)  d_in[1];
    const float* W1  = (const float*)d_in[2];
    const float* b1  = (const float*)d_in[3];
    const float* Wf  = (const float*)d_in[4];
    const float* bf  = (const float*)d_in[5];
    const float* Wa  = (const float*)d_in[6];
    const float* ba  = (const float*)d_in[7];
    const float* Wb  = (const float*)d_in[8];
    const float* bb  = (const float*)d_in[9];
    const float* Wc  = (const float*)d_in[10];
    const float* bc  = (const float*)d_in[11];

    cudaFuncSetAttribute(k_gemm_seg, cudaFuncAttributeMaxDynamicSharedMemorySize, SMEM_DYN);

    k_w1cvt<<<256, 256>>>(W1);
    k_gemm_seg<<<NCTA, 256, SMEM_DYN>>>(x, cid, b1);
    k_reduce<<<64, 256>>>();
    k_head1<<<64, 256>>>(Wf, bf);
    k_head2<<<64, 256>>>(Wa, ba, Wb, bb, Wc);
    k_final<<<1, 256>>>(bc, (float*)d_out);
}

// round 5
// speedup vs baseline: 1.3800x; 1.3800x over previous
#include <cuda_runtime.h>
#include <cuda_bf16.h>
#include <cstdint>
#include <math.h>

#define NQ     65536
#define DIMIN  1024
#define DIMH   256
#define NCLUS  8
#define BM     128
#define BN     256
#define BK     64
#define NBLK   (NQ / BM)       // 512
#define NITER  (DIMIN / BK)    // 16

// smem layout (bytes)
#define LDA      144           // 64 bf16 (128B) + 16B pad
#define STAGE_A  (128 * LDA)   // 18432
#define STAGE_B  (256 * LDA)   // 36864
#define STAGE    (STAGE_A + STAGE_B)
#define OFF_A(s) ((unsigned)(s) * STAGE)
#define OFF_B(s) ((unsigned)(s) * STAGE + STAGE_A)
#define HLD      260
#define OFF_EXTRA 133120u      // hbuf 128*260*4, unioned with 2 stages (110592)
#define OFF_B1   OFF_EXTRA
#define OFF_CID  (OFF_B1 + 1024u)
#define OFF_CNT  (OFF_CID + 512u)
#define SMEM_DYN (OFF_CNT + 32u)   // ~134.7 KB -> 1 CTA/SM

// ---- device scratch ----
__device__ __nv_bfloat16 g_W1bf[DIMH * DIMIN];        // 512 KB
__device__ float g_scratch[NBLK * NCLUS * DIMH];      // 4 MB
__device__ int   g_scnt[NBLK * NCLUS];
__device__ float g_seg[NCLUS * DIMH];
__device__ int   g_cnt[NCLUS];
__device__ float g_hp[NCLUS * DIMH];
__device__ float g_part[NCLUS * 8];

// ---- helpers ----
__device__ __forceinline__ uint32_t smem_u32(const void* p) {
    uint32_t a;
    asm("{ .reg .u64 t; cvta.to.shared.u64 t, %1; cvt.u32.u64 %0, t; }" : "=r"(a) : "l"(p));
    return a;
}

__device__ __forceinline__ void ldm4(uint32_t* r, uint32_t addr) {
    asm volatile("ldmatrix.sync.aligned.m8n8.x4.shared.b16 {%0,%1,%2,%3}, [%4];"
                 : "=r"(r[0]), "=r"(r[1]), "=r"(r[2]), "=r"(r[3]) : "r"(addr));
}

__device__ __forceinline__ void mma_bf16(float* d, const uint32_t* a,
                                         uint32_t b0, uint32_t b1) {
    asm volatile("mma.sync.aligned.m16n8k16.row.col.f32.bf16.bf16.f32 "
                 "{%0,%1,%2,%3}, {%4,%5,%6,%7}, {%8,%9}, {%0,%1,%2,%3};"
                 : "+f"(d[0]), "+f"(d[1]), "+f"(d[2]), "+f"(d[3])
                 : "r"(a[0]), "r"(a[1]), "r"(a[2]), "r"(a[3]), "r"(b0), "r"(b1));
}

// B tile: 256 rows x 64 bf16 = 2048 x 16B chunks, 8 per thread (256 thr)
__device__ __forceinline__ void cp_B(uint32_t base, int s, int k0, int tid) {
    uint32_t dst = base + OFF_B(s);
    const char* src = (const char*)g_W1bf + (size_t)k0 * 2;
    #pragma unroll
    for (int i = 0; i < 8; i++) {
        int c  = tid + 256 * i;
        int n  = c >> 3, kc = c & 7;
        uint32_t d = dst + (unsigned)n * LDA + (unsigned)kc * 16;
        const void* g = src + (size_t)n * (DIMIN * 2) + kc * 16;
        asm volatile("cp.async.cg.shared.global [%0], [%1], 16;" :: "r"(d), "l"(g));
    }
}

// A half-tile (64 rows) load / store, 4 float4 per thread
__device__ __forceinline__ void ldgA(float4* areg, const float* x,
                                     int row0, int it, int tid, int h) {
    const int r0 = h * 64 + (tid >> 4), fc = tid & 15;
    const float* p = x + (size_t)(row0 + r0) * DIMIN + it * BK + fc * 4;
    #pragma unroll
    for (int i = 0; i < 4; i++)
        areg[i] = *(const float4*)(p + (size_t)(16 * i) * DIMIN);
}

__device__ __forceinline__ void stsA(uint32_t sA, const float4* areg, int tid, int h) {
    const int r0 = h * 64 + (tid >> 4), fc = tid & 15;
    #pragma unroll
    for (int i = 0; i < 4; i++) {
        __nv_bfloat162 lo = __floats2bfloat162_rn(areg[i].x, areg[i].y);
        __nv_bfloat162 hi = __floats2bfloat162_rn(areg[i].z, areg[i].w);
        uint32_t u0 = *(uint32_t*)&lo, u1 = *(uint32_t*)&hi;
        uint32_t d = sA + (unsigned)(r0 + 16 * i) * LDA + (unsigned)fc * 8;
        asm volatile("st.shared.v2.b32 [%0], {%1,%2};" :: "r"(d), "r"(u0), "r"(u1));
    }
}

// ---------------------------------------------------------------------------
// K0: W1 fp32 -> bf16
// ---------------------------------------------------------------------------
__global__ __launch_bounds__(256)
void k_w1cvt(const float* __restrict__ W1) {
    int i = (blockIdx.x * 256 + threadIdx.x) * 4;
    float4 v = *(const float4*)(W1 + i);
    __nv_bfloat162 lo = __floats2bfloat162_rn(v.x, v.y);
    __nv_bfloat162 hi = __floats2bfloat162_rn(v.z, v.w);
    uint2 u;
    u.x = *(uint32_t*)&lo;
    u.y = *(uint32_t*)&hi;
    *(uint2*)&g_W1bf[i] = u;
}

// ---------------------------------------------------------------------------
// K1: bf16 mma GEMM 128x256 per CTA, 256 thr (8 warps, warp tile 64x64)
//     fused bias+relu+cluster sums
// ---------------------------------------------------------------------------
__global__ __launch_bounds__(256, 1)
void k_gemm_seg(const float* __restrict__ x, const int* __restrict__ cid,
                const float* __restrict__ b1)
{
    extern __shared__ char sm[];
    const uint32_t base = smem_u32(sm);
    float* b1s   = (float*)(sm + OFF_B1);
    int*   cid_s = (int*)  (sm + OFF_CID);
    int*   cnt_s = (int*)  (sm + OFF_CNT);

    const int tid  = threadIdx.x;
    const int lane = tid & 31, warp = tid >> 5;
    const int wn = warp & 3, wm = warp >> 2;   // 4 n-groups x 2 m-groups (64x64 tiles)
    const int row0 = blockIdx.x * BM;

    if (tid < 8)   cnt_s[tid] = 0;
    b1s[tid] = b1[tid];
    if (tid < 128) cid_s[tid] = cid[row0 + tid];

    float acc[4][8][4];
    #pragma unroll
    for (int mt = 0; mt < 4; mt++)
        #pragma unroll
        for (int nt = 0; nt < 8; nt++)
            #pragma unroll
            for (int q = 0; q < 4; q++) acc[mt][nt][q] = 0.0f;

    // prologue
    float4 areg[4];
    cp_B(base, 0, 0, tid);
    asm volatile("cp.async.commit_group;" ::: "memory");
    ldgA(areg, x, row0, 0, tid, 0);
    stsA(base + OFF_A(0), areg, tid, 0);
    ldgA(areg, x, row0, 0, tid, 1);
    stsA(base + OFF_A(0), areg, tid, 1);
    asm volatile("cp.async.wait_group 0;" ::: "memory");
    __syncthreads();

    for (int it = 0; it < NITER; it++) {
        const int s = it & 1;
        const bool nxt = (it + 1 < NITER);
        if (nxt) {
            cp_B(base, s ^ 1, (it + 1) * BK, tid);
            asm volatile("cp.async.commit_group;" ::: "memory");
            ldgA(areg, x, row0, it + 1, tid, 0);
        }
        const uint32_t sA = base + OFF_A(s), sB = base + OFF_B(s);

        #pragma unroll
        for (int half = 0; half < 2; half++) {
            #pragma unroll
            for (int kq = 0; kq < 2; kq++) {
                const int ks = half * 2 + kq;
                uint32_t a[4][4];
                const uint32_t abase = sA + (unsigned)(wm * 64 + (lane & 15)) * LDA
                                     + (unsigned)ks * 32 + (unsigned)(lane >> 4) * 16;
                #pragma unroll
                for (int mt = 0; mt < 4; mt++)
                    ldm4(a[mt], abase + (unsigned)(mt * 16) * LDA);
                #pragma unroll
                for (int j = 0; j < 4; j++) {
                    uint32_t b[4];
                    ldm4(b, sB + (unsigned)(wn * 64 + j * 16 + (lane & 15)) * LDA
                              + (unsigned)ks * 32 + (unsigned)(lane >> 4) * 16);
                    #pragma unroll
                    for (int mt = 0; mt < 4; mt++) {
                        mma_bf16(acc[mt][2 * j],     a[mt], b[0], b[2]);
                        mma_bf16(acc[mt][2 * j + 1], a[mt], b[1], b[3]);
                    }
                }
            }
            if (nxt) {
                stsA(base + OFF_A(s ^ 1), areg, tid, half);
                if (half == 0) ldgA(areg, x, row0, it + 1, tid, 1);
                else asm volatile("cp.async.wait_group 0;" ::: "memory");
            }
        }
        __syncthreads();
    }

    // epilogue: accum -> smem hbuf (unioned with stage region)
    float* hbuf = (float*)sm;
    #pragma unroll
    for (int mt = 0; mt < 4; mt++)
        #pragma unroll
        for (int nt = 0; nt < 8; nt++) {
            int gm = wm * 64 + mt * 16 + (lane >> 2);
            int gn = wn * 64 + nt * 8 + 2 * (lane & 3);
            hbuf[gm * HLD + gn]           = acc[mt][nt][0];
            hbuf[gm * HLD + gn + 1]       = acc[mt][nt][1];
            hbuf[(gm + 8) * HLD + gn]     = acc[mt][nt][2];
            hbuf[(gm + 8) * HLD + gn + 1] = acc[mt][nt][3];
        }

    // cluster counts (warps 0-3 cover the 128 rows)
    if (tid < 128) {
        int cidv = cid_s[tid];
        #pragma unroll
        for (int c = 0; c < 8; c++) {
            unsigned m = __ballot_sync(0xffffffffu, cidv == c);
            if (lane == c) atomicAdd(&cnt_s[c], __popc(m));
        }
    }
    __syncthreads();

    // bias + relu + cluster-masked column sums: thread = column
    const float bt = b1s[tid];
    float sacc[NCLUS];
    #pragma unroll
    for (int c = 0; c < NCLUS; c++) sacc[c] = 0.0f;
    #pragma unroll 4
    for (int r = 0; r < 128; r++) {
        float v = fmaxf(hbuf[r * HLD + tid] + bt, 0.0f);
        int cd = cid_s[r];
        #pragma unroll
        for (int c = 0; c < NCLUS; c++) sacc[c] += (cd == c) ? v : 0.0f;
    }
    float* outp = g_scratch + (size_t)blockIdx.x * (NCLUS * DIMH) + tid;
    #pragma unroll
    for (int c = 0; c < NCLUS; c++) outp[c * DIMH] = sacc[c];
    if (tid < 8) g_scnt[blockIdx.x * 8 + tid] = cnt_s[tid];
}

// ---------------------------------------------------------------------------
// K2: reduce 512 block partials -> g_seg ; counts -> g_cnt
// ---------------------------------------------------------------------------
__global__ __launch_bounds__(256)
void k_reduce()
{
    const int g0 = blockIdx.x * 32;
    const int jj = threadIdx.x & 31;
    const int bs = threadIdx.x >> 5;
    float s = 0.0f;
    #pragma unroll 4
    for (int b = bs; b < NBLK; b += 8)
        s += g_scratch[(size_t)b * (NCLUS * DIMH) + g0 + jj];
    __shared__ float red[8][33];
    __shared__ int   credp[8][9];
    red[bs][jj] = s;
    if (blockIdx.x == 0 && threadIdx.x < 64) {
        int c = threadIdx.x & 7, sl = threadIdx.x >> 3, t = 0;
        for (int b = sl; b < NBLK; b += 8) t += g_scnt[b * 8 + c];
        credp[c][sl] = t;
    }
    __syncthreads();
    if (bs == 0) {
        float t = 0.0f;
        #pragma unroll
        for (int c = 0; c < 8; c++) t += red[c][jj];
        g_seg[g0 + jj] = t;
    }
    if (blockIdx.x == 0 && threadIdx.x < 8) {
        int T = 0;
        #pragma unroll
        for (int sl = 0; sl < 8; sl++) T += credp[threadIdx.x][sl];
        g_cnt[threadIdx.x] = T;
    }
}

// ---------------------------------------------------------------------------
// K3a: means + h_path = relu(hc @ Wf^T + bf)   grid 64 (8 clus x 8 row-groups)
// ---------------------------------------------------------------------------
__global__ __launch_bounds__(256)
void k_head1(const float* __restrict__ Wf, const float* __restrict__ bfv)
{
    const int c = blockIdx.x >> 3, og = blockIdx.x & 7, tid = threadIdx.x;
    __shared__ float hc_s[DIMH];
    float denom = fmaxf((float)g_cnt[c], 1.0f);
    hc_s[tid] = g_seg[c * DIMH + tid] * (1.0f / denom);
    __syncthreads();

    const int row = og * 32 + (tid >> 3);
    const int k0  = (tid & 7) * 32;
    const float4* w = (const float4*)(Wf + (size_t)row * DIMH + k0);
    float a = 0.0f;
    #pragma unroll
    for (int k = 0; k < 8; k++) {
        float4 wv = w[k];
        a += wv.x * hc_s[k0 + 4 * k]     + wv.y * hc_s[k0 + 4 * k + 1]
           + wv.z * hc_s[k0 + 4 * k + 2] + wv.w * hc_s[k0 + 4 * k + 3];
    }
    #pragma unroll
    for (int o = 4; o > 0; o >>= 1)
        a += __shfl_xor_sync(0xffffffffu, a, o);
    if ((tid & 7) == 0)
        g_hp[c * DIMH + row] = fmaxf(a + bfv[row], 0.0f);
}

// ---------------------------------------------------------------------------
// K3b: gated attention partial logits   grid 64 (8 clus x 8 row-groups)
// ---------------------------------------------------------------------------
__global__ __launch_bounds__(256)
void k_head2(const float* __restrict__ Wa, const float* __restrict__ ba,
             const float* __restrict__ Wb, const float* __restrict__ bb,
             const float* __restrict__ Wc)
{
    const int b = blockIdx.x, tid = threadIdx.x;
    const int c = b >> 3, rg = b & 7;
    __shared__ float hp_s[DIMH];
    hp_s[tid] = g_hp[c * DIMH + tid];
    __syncthreads();

    const int row = rg * 32 + (tid >> 3);
    const int k0  = (tid & 7) * 32;
    const float4* wa = (const float4*)(Wa + (size_t)row * DIMH + k0);
    const float4* wb = (const float4*)(Wb + (size_t)row * DIMH + k0);
    float aa = 0.0f, gg = 0.0f;
    #pragma unroll
    for (int k = 0; k < 8; k++) {
        float4 av = wa[k], bv = wb[k];
        float h0 = hp_s[k0 + 4 * k], h1 = hp_s[k0 + 4 * k + 1];
        float h2 = hp_s[k0 + 4 * k + 2], h3 = hp_s[k0 + 4 * k + 3];
        aa += av.x * h0 + av.y * h1 + av.z * h2 + av.w * h3;
        gg += bv.x * h0 + bv.y * h1 + bv.z * h2 + bv.w * h3;
    }
    #pragma unroll
    for (int o = 4; o > 0; o >>= 1) {
        aa += __shfl_xor_sync(0xffffffffu, aa, o);
        gg += __shfl_xor_sync(0xffffffffu, gg, o);
    }
    float val = 0.0f;
    if ((tid & 7) == 0) {
        aa += ba[row]; gg += bb[row];
        val = tanhf(aa) * (1.0f / (1.0f + expf(-gg))) * Wc[row];
    }
    val += __shfl_xor_sync(0xffffffffu, val, 8);
    val += __shfl_xor_sync(0xffffffffu, val, 16);
    __shared__ float wred[8];
    if ((tid & 31) == 0) wred[tid >> 5] = val;
    __syncthreads();
    if (tid == 0) {
        float t = 0.0f;
        #pragma unroll
        for (int w = 0; w < 8; w++) t += wred[w];
        g_part[c * 8 + rg] = t;
    }
}

// ---------------------------------------------------------------------------
// K3c: softmax + weighted sum -> out[256]
// ---------------------------------------------------------------------------
__global__ __launch_bounds__(256)
void k_final(const float* __restrict__ bc, float* __restrict__ out)
{
    const int tid = threadIdx.x;
    float l[NCLUS];
    #pragma unroll
    for (int c = 0; c < NCLUS; c++) {
        float t = bc[0];
        #pragma unroll
        for (int g = 0; g < 8; g++) t += g_part[c * 8 + g];
        l[c] = t;
    }
    float m = -1e30f;
    #pragma unroll
    for (int c = 0; c < NCLUS; c++) m = fmaxf(m, l[c]);
    float S = 0.0f;
    #pragma unroll
    for (int c = 0; c < NCLUS; c++) { l[c] = expf(l[c] - m); S += l[c]; }
    float o = 0.0f;
    #pragma unroll
    for (int c = 0; c < NCLUS; c++) o += l[c] * g_hp[c * DIMH + tid];
    out[tid] = o / S;
}

// ---------------------------------------------------------------------------
extern "C" void kernel_launch(void* const* d_in, const int* in_sizes, int n_in,
                              void* d_out, int out_size)
{
    const float* x   = (const float*)d_in[0];
    const int*   cid = (const int*)  d_in[1];
    const float* W1  = (const float*)d_in[2];
    const float* b1  = (const float*)d_in[3];
    const float* Wf  = (const float*)d_in[4];
    const float* bf  = (const float*)d_in[5];
    const float* Wa  = (const float*)d_in[6];
    const float* ba  = (const float*)d_in[7];
    const float* Wb  = (const float*)d_in[8];
    const float* bb  = (const float*)d_in[9];
    const float* Wc  = (const float*)d_in[10];
    const float* bc  = (const float*)d_in[11];

    cudaFuncSetAttribute(k_gemm_seg, cudaFuncAttributeMaxDynamicSharedMemorySize, SMEM_DYN);

    k_w1cvt<<<256, 256>>>(W1);
    k_gemm_seg<<<NBLK, 256, SMEM_DYN>>>(x, cid, b1);
    k_reduce<<<64, 256>>>();
    k_head1<<<64, 256>>>(Wf, bf);
    k_head2<<<64, 256>>>(Wa, ba, Wb, bb, Wc);
    k_final<<<1, 256>>>(bc, (float*)d_out);
}